// round 12
// baseline (speedup 1.0000x reference)
#include <cuda_runtime.h>
#include <math.h>

#define NB 16
#define NT 2048
#define ND 512
#define NH 512
#define SIXH 3072
#define MROWS (NB * NT)   // 32768

#define NREC 64           // recurrence CTAs (8 channels each)
#define NGEMM 84          // gemm worker CTAs
#define NBLK (NREC + NGEMM)   // 148 == SM count -> all co-resident @ 1 CTA/SM
#define THR2 256

#define NSLAB 16
#define TILES_TOTAL 6144      // 16 b x 16 tau x 24 n
#define TILES_PER_SLAB 384    // 16 b x 24 n

// rec smem: sh_hA 4096 | sh_hB 4096 | sh_wt 512*48 | red 1440 u64 (2880 f)
#define SMEM2_FLOATS (4096 + 4096 + 24576 + 2880)
#define SMEM2_BYTES (SMEM2_FLOATS * 4)

typedef unsigned long long u64;

// ---------------- device scratch ----------------
__device__ float g_pi[(size_t)MROWS * SIXH];   // PI = X @ W^T + b
__device__ float g_htA[2][ND * 8];             // chain A h (batches 0-7), [k][b]
__device__ float g_htB[2][ND * 8];             // chain B h (batches 8-15)
__device__ u64 g_cntA;                         // chain A step counter (monotonic)
__device__ u64 g_cntB;                         // chain B step counter
__device__ u64 g_init_cnt;                     // init barrier (148 CTAs)
__device__ u64 g_slab_cnt[NSLAB];              // slab-complete counters

// ---------------- packed f32x2 helpers ----------------
__device__ __forceinline__ u64 pack2(float lo, float hi) {
    u64 r;
    asm("mov.b64 %0, {%1, %2};" : "=l"(r) : "f"(lo), "f"(hi));
    return r;
}
__device__ __forceinline__ void unpack2(u64 v, float& lo, float& hi) {
    asm("mov.b64 {%0, %1}, %2;" : "=f"(lo), "=f"(hi) : "l"(v));
}
__device__ __forceinline__ void fma2(u64& d, u64 a, u64 b) {
    asm("fma.rn.f32x2 %0, %1, %2, %0;" : "+l"(d) : "l"(a), "l"(b));
}
__device__ __forceinline__ u64 add2(u64 a, u64 b) {
    u64 r;
    asm("add.rn.f32x2 %0, %1, %2;" : "=l"(r) : "l"(a), "l"(b));
    return r;
}

__device__ __forceinline__ float sigf(float x) {
    return 1.0f / (1.0f + __expf(-x));
}
__device__ __forceinline__ float tanh_acc(float x) {
    float e = __expf(-2.0f * fabsf(x));
    float t = (1.0f - e) / (1.0f + e);
    return x >= 0.0f ? t : -t;
}

// init barrier across ALL 148 CTAs (monotonic, replay-safe)
__device__ __forceinline__ void init_barrier_all() {
    __syncthreads();
    if (threadIdx.x == 0) {
        __threadfence();
        u64 arrive = atomicAdd(&g_init_cnt, 1ULL);
        u64 target = (arrive / NBLK + 1ULL) * NBLK;
        if (arrive + 1ULL != target) {
            volatile u64* p = (volatile u64*)&g_init_cnt;
            while (*p < target) { }
        }
        __threadfence();
    }
    __syncthreads();
}

#define BK1 16
#define LDA1 132

// =====================================================================
// Fused kernel: blocks 0-63 = dual-chain recurrence, blocks 64-147 =
// gemm workers filling g_pi slab-by-slab (tau-ascending).
// =====================================================================
__global__ void __launch_bounds__(THR2, 1) fused_lstm_kernel(
    const float* __restrict__ X, const float* __restrict__ W,
    const float* __restrict__ bias, const int* __restrict__ lengths,
    float* __restrict__ out)
{
    extern __shared__ float smem[];
    const int tid = threadIdx.x;
    const int cta = blockIdx.x;

    if (cta >= NREC) {
        // ================== GEMM worker (unchanged) ==================
        float* As = smem;
        float* Bs = smem + BK1 * LDA1;
        const int w = cta - NREC;
        const int tx = tid & 15, ty = tid >> 4;

        init_barrier_all();

        for (int it = w; it < TILES_TOTAL; it += NGEMM) {
            const int tau = it / TILES_PER_SLAB;
            const int r = it % TILES_PER_SLAB;
            const int b = r / 24;
            const int n = r % 24;
            const int n0 = n * 128;
            const size_t m0 = (size_t)b * NT + (size_t)tau * 128;

            const float* Xp = X + m0 * ND;
            const float* Wp = W + (size_t)n0 * ND;

            u64 accP[8][4];
#pragma unroll
            for (int i = 0; i < 8; i++)
#pragma unroll
                for (int j = 0; j < 4; j++) accP[i][j] = 0ULL;

            for (int kc = 0; kc < ND; kc += BK1) {
#pragma unroll
                for (int i = 0; i < 2; i++) {
                    int idx4 = tid + 256 * i;
                    int row = idx4 >> 2;
                    int kq = idx4 & 3;
                    float4 va = *(const float4*)(Xp + (size_t)row * ND + kc + kq * 4);
                    float4 vb = *(const float4*)(Wp + (size_t)row * ND + kc + kq * 4);
                    As[(kq * 4 + 0) * LDA1 + row] = va.x;
                    As[(kq * 4 + 1) * LDA1 + row] = va.y;
                    As[(kq * 4 + 2) * LDA1 + row] = va.z;
                    As[(kq * 4 + 3) * LDA1 + row] = va.w;
                    Bs[(kq * 4 + 0) * LDA1 + row] = vb.x;
                    Bs[(kq * 4 + 1) * LDA1 + row] = vb.y;
                    Bs[(kq * 4 + 2) * LDA1 + row] = vb.z;
                    Bs[(kq * 4 + 3) * LDA1 + row] = vb.w;
                }
                __syncthreads();
#pragma unroll
                for (int k = 0; k < BK1; k++) {
                    float a[8];
                    *(float4*)&a[0] = *(const float4*)&As[k * LDA1 + ty * 8];
                    *(float4*)&a[4] = *(const float4*)&As[k * LDA1 + ty * 8 + 4];
                    ulonglong2 b01 = *(const ulonglong2*)&Bs[k * LDA1 + tx * 8];
                    ulonglong2 b23 = *(const ulonglong2*)&Bs[k * LDA1 + tx * 8 + 4];
#pragma unroll
                    for (int i = 0; i < 8; i++) {
                        u64 ad = pack2(a[i], a[i]);
                        fma2(accP[i][0], b01.x, ad);
                        fma2(accP[i][1], b01.y, ad);
                        fma2(accP[i][2], b23.x, ad);
                        fma2(accP[i][3], b23.y, ad);
                    }
                }
                __syncthreads();
            }

            float bv[8];
#pragma unroll
            for (int j = 0; j < 8; j++) bv[j] = bias[n0 + tx * 8 + j];
#pragma unroll
            for (int i = 0; i < 8; i++) {
                float c[8];
#pragma unroll
                for (int jp = 0; jp < 4; jp++)
                    unpack2(accP[i][jp], c[2 * jp], c[2 * jp + 1]);
                size_t m = m0 + ty * 8 + i;
                float* op = g_pi + m * SIXH + n0 + tx * 8;
                float4 r0 = make_float4(c[0] + bv[0], c[1] + bv[1],
                                        c[2] + bv[2], c[3] + bv[3]);
                float4 r1 = make_float4(c[4] + bv[4], c[5] + bv[5],
                                        c[6] + bv[6], c[7] + bv[7]);
                *(float4*)op = r0;
                *(float4*)(op + 4) = r1;
            }

            __threadfence();
            __syncthreads();
            if (tid == 0) {
                asm volatile("red.release.gpu.global.add.u64 [%0], 1;"
                             :: "l"(&g_slab_cnt[tau]) : "memory");
            }
        }
        return;
    }

    // ============ dual-chain recurrence CTA: 8 channels ============
    float* sh_hA = smem;                   // [512][8] chain A staging
    float* sh_hB = smem + 4096;            // [512][8] chain B staging
    float* sh_wt = smem + 8192;            // [512][48]: [k][jp*12 + g*2 + c]
    u64*   red   = (u64*)(smem + 8192 + 24576);  // [8b*5g*4jp][9] pairs
    __shared__ u64 s_slab[NSLAB];
    __shared__ u64 s_base[2];

    const int jo_base = cta * 8;

    // persistent W slice (channel-pair layout, same as R11)
    for (int p = tid; p < 40 * 512; p += THR2) {
        int k = p & 511;
        int r = p >> 9;          // 0..39
        int g = r / 8;
        int rc = r & 7;
        int jp = rc >> 1, c = rc & 1;
        sh_wt[k * 48 + jp * 12 + g * 2 + c] =
            W[(size_t)(g * NH + jo_base + 2 * jp + c) * ND + k];
    }

    // read counter bases BEFORE any arrivals
    if (tid < NSLAB) {
        u64 v;
        asm volatile("ld.global.cg.u64 %0, [%1];" : "=l"(v)
                     : "l"(&g_slab_cnt[tid]) : "memory");
        s_slab[tid] = v;
    }
    if (tid == 0) {
        u64 a, b;
        asm volatile("ld.global.cg.u64 %0, [%1];" : "=l"(a)
                     : "l"(&g_cntA) : "memory");
        asm volatile("ld.global.cg.u64 %0, [%1];" : "=l"(b)
                     : "l"(&g_cntB) : "memory");
        s_base[0] = a;
        s_base[1] = b;
    }

    // combine-thread persistent state (64 threads: b_c = tid>>3, ch = tid&7)
    int b_c = 0, jo_c = 0, lenA = 0, lenB = 0;
    float bias5[5] = {0, 0, 0, 0, 0};
    float cA = 0.0f, cB = 0.0f;
    if (tid < 64) {
        b_c = tid >> 3;
        jo_c = jo_base + (tid & 7);
#pragma unroll
        for (int g = 0; g < 5; g++) bias5[g] = bias[g * NH + jo_c];
        lenA = lengths[b_c];
        lenB = lengths[8 + b_c];
    }

    // publish h_0 = zeros for both chains (64 values each per CTA)
    if (tid < 64) {
        g_htA[0][jo_base * 8 + tid] = 0.0f;
        g_htB[0][jo_base * 8 + tid] = 0.0f;
    }
    init_barrier_all();   // fences make zeros + bases globally visible

    const u64 baseA = s_base[0];
    const u64 baseB = s_base[1];

    const int warp = tid >> 5, lane = tid & 31;
    const int ks = lane >> 4;          // K sub-split (32 k each)
    const int bg = (lane >> 2) & 3;    // batch pair {2bg, 2bg+1} (of 8)
    const int jp = lane & 3;           // channel pair {2jp, 2jp+1}
    const int krow0 = warp * 64 + ks * 32;
    const float* wp0 = sh_wt + (size_t)krow0 * 48 + jp * 12;

    // one chain segment (inlined twice per t via lambda)
    auto segment = [&](float (*ht)[ND * 8], u64* cnt, u64 cbase,
                       float* sh_h, int batch0, int len_c, float& c_st,
                       int t) {
        // prefetch PI(t) (flies during spin)
        float pi5[5] = {0, 0, 0, 0, 0}, pi6 = 0.0f;
        if (tid < 64) {
            const float* pr =
                g_pi + ((size_t)(batch0 + b_c) * NT + t) * SIXH + jo_c;
#pragma unroll
            for (int g = 0; g < 5; g++) pi5[g] = pr[g * NH];
            pi6 = pr[5 * NH];
        }
        // wait for h(t): published by all 64 CTAs
        if (t > 0 && tid == 0) {
            u64 tgt = cbase + (u64)NREC * (u64)t;
            u64 v;
            do {
                asm volatile("ld.global.acquire.gpu.u64 %0, [%1];"
                             : "=l"(v) : "l"(cnt) : "memory");
            } while (v < tgt);
        }
        __syncthreads();

        // stage h(t) [512][8] via L2-direct loads (16KB)
        {
            const float4* src = (const float4*)(ht[t & 1]);
            float4* dst = (float4*)sh_h;
#pragma unroll
            for (int i = 0; i < 4; i++)
                dst[tid + i * 256] = __ldcg(src + tid + i * 256);
        }
        __syncthreads();

        // K-split packed GEMM: 2 batches x 5 gates x {2 ch}, 32 k per lane
        u64 acc[10];
#pragma unroll
        for (int i = 0; i < 10; i++) acc[i] = 0ULL;
        {
            const u64* hp = (const u64*)sh_h + (size_t)krow0 * 4 + bg;
            const float* wp = wp0;
#pragma unroll 8
            for (int kk = 0; kk < 32; kk++) {
                u64 hd = *hp;                                  // {h_b0, h_b1}
                float h0, h1;
                unpack2(hd, h0, h1);
                u64 h00 = pack2(h0, h0);
                u64 h11 = pack2(h1, h1);
                ulonglong2 wA = *(const ulonglong2*)wp;        // g0,g1:{c0,c1}
                ulonglong2 wB = *(const ulonglong2*)(wp + 4);  // g2,g3
                u64 wC = *(const u64*)(wp + 8);                // g4
                fma2(acc[0], wA.x, h00);
                fma2(acc[1], wA.y, h00);
                fma2(acc[2], wB.x, h00);
                fma2(acc[3], wB.y, h00);
                fma2(acc[4], wC, h00);
                fma2(acc[5], wA.x, h11);
                fma2(acc[6], wA.y, h11);
                fma2(acc[7], wB.x, h11);
                fma2(acc[8], wB.y, h11);
                fma2(acc[9], wC, h11);
                hp += 4;
                wp += 48;
            }
        }
        // fold ks halves (xor 16)
#pragma unroll
        for (int i = 0; i < 10; i++)
            acc[i] = add2(acc[i], __shfl_xor_sync(0xffffffffu, acc[i], 16));
        if (ks == 0) {
            int rb0 = ((2 * bg) * 5) * 4 + jp;
            int rb1 = ((2 * bg + 1) * 5) * 4 + jp;
#pragma unroll
            for (int g = 0; g < 5; g++) {
                red[(rb0 + g * 4) * 9 + warp] = acc[g];
                red[(rb1 + g * 4) * 9 + warp] = acc[5 + g];
            }
        }
        __syncthreads();

        // reduce across 8 warps + gate math + publish (64 threads)
        if (tid < 64) {
            const float* redf = (const float*)red;
            int jpc = (tid & 7) >> 1, e = tid & 1;
            float gv[5];
#pragma unroll
            for (int g = 0; g < 5; g++) {
                const float* rp = redf + (((b_c * 5 + g) * 4 + jpc) * 9) * 2 + e;
                float s = ((rp[0] + rp[2]) + (rp[4] + rp[6])) +
                          ((rp[8] + rp[10]) + (rp[12] + rp[14]));
                gv[g] = s + bias5[g] + pi5[g];
            }
            float ig = sigf(gv[0]);
            float fg = sigf(gv[1]);
            float mi = tanh_acc(gv[2]);
            float og = sigf(gv[3]);
            float hwg = sigf(gv[4]);
            float mem = fmaf(ig, mi, fg * c_st);
            float o_ = og * tanh_acc(mem);
            o_ = fmaf(hwg, o_ - pi6, pi6);
            if (t >= len_c) { o_ = 0.0f; mem = 0.0f; }
            c_st = mem;

            ht[(t + 1) & 1][jo_c * 8 + b_c] = o_;   // transposed publish
            out[((size_t)(batch0 + b_c) * NT + t) * NH + jo_c] = o_;
        }
        __syncthreads();
        // arrive: h(t+1) published by this CTA
        if (tid == 0) {
            __threadfence();
            asm volatile("red.release.gpu.global.add.u64 [%0], 1;"
                         :: "l"(cnt) : "memory");
        }
    };

    for (int t = 0; t < NT; t++) {
        // slab gate before each 128-step PI slab (covers both chains)
        if ((t & 127) == 0) {
            if (tid == 0) {
                int tau = t >> 7;
                u64 tgt = s_slab[tau] + (u64)TILES_PER_SLAB;
                u64 v;
                do {
                    asm volatile("ld.global.acquire.gpu.u64 %0, [%1];"
                                 : "=l"(v) : "l"(&g_slab_cnt[tau]) : "memory");
                } while (v < tgt);
            }
            __syncthreads();
        }
        segment(g_htA, &g_cntA, baseA, sh_hA, 0, lenA, cA, t);
        segment(g_htB, &g_cntB, baseB, sh_hB, 8, lenB, cB, t);
    }
}

// =====================================================================
// launch
// =====================================================================
extern "C" void kernel_launch(void* const* d_in, const int* in_sizes, int n_in,
                              void* d_out, int out_size) {
    const float* x = (const float*)d_in[0];
    const int* lengths = (const int*)d_in[1];
    const float* W = (const float*)d_in[2];
    const float* bias = (const float*)d_in[3];
    float* out = (float*)d_out;

    static bool attr_done = false;
    if (!attr_done) {
        cudaFuncSetAttribute(fused_lstm_kernel,
                             cudaFuncAttributeMaxDynamicSharedMemorySize,
                             SMEM2_BYTES);
        attr_done = true;
    }

    fused_lstm_kernel<<<NBLK, THR2, SMEM2_BYTES>>>(x, W, bias, lengths, out);
}

// round 13
// speedup vs baseline: 1.3361x; 1.3361x over previous
#include <cuda_runtime.h>
#include <math.h>

#define NB 16
#define NT 2048
#define ND 512
#define NH 512
#define SIXH 3072
#define MROWS (NB * NT)   // 32768

#define NREC 64           // recurrence CTAs (8 channels each)
#define NGEMM 84          // gemm worker CTAs
#define NBLK (NREC + NGEMM)   // 148 == SM count -> all co-resident @ 1 CTA/SM
#define THR2 256

#define NSLAB 16
#define TILES_TOTAL 6144      // 16 b x 16 tau x 24 n
#define TILES_PER_SLAB 384    // 16 b x 24 n

// rec smem: sh_wt 512*48 floats | red 2880 u64 (5760 floats)
#define SMEM2_FLOATS (24576 + 5760)
#define SMEM2_BYTES (SMEM2_FLOATS * 4)

typedef unsigned long long u64;

// ---------------- device scratch ----------------
__device__ float g_pi[(size_t)MROWS * SIXH];   // PI = X @ W^T + b
__device__ u64 g_h2[2][ND * NB];               // pre-splatted h: [k][b] = {h,h}
__device__ u64 g_cnt;                          // step counter (monotonic)
__device__ u64 g_init_cnt;                     // init barrier (148 CTAs)
__device__ u64 g_slab_cnt[NSLAB];              // slab-complete counters

// ---------------- packed f32x2 helpers ----------------
__device__ __forceinline__ u64 pack2(float lo, float hi) {
    u64 r;
    asm("mov.b64 %0, {%1, %2};" : "=l"(r) : "f"(lo), "f"(hi));
    return r;
}
__device__ __forceinline__ void unpack2(u64 v, float& lo, float& hi) {
    asm("mov.b64 {%0, %1}, %2;" : "=f"(lo), "=f"(hi) : "l"(v));
}
__device__ __forceinline__ void fma2(u64& d, u64 a, u64 b) {
    asm("fma.rn.f32x2 %0, %1, %2, %0;" : "+l"(d) : "l"(a), "l"(b));
}

__device__ __forceinline__ float sigf(float x) {
    return 1.0f / (1.0f + __expf(-x));
}
__device__ __forceinline__ float tanh_acc(float x) {
    float e = __expf(-2.0f * fabsf(x));
    float t = (1.0f - e) / (1.0f + e);
    return x >= 0.0f ? t : -t;
}

// init barrier across ALL 148 CTAs (monotonic, replay-safe)
__device__ __forceinline__ void init_barrier_all() {
    __syncthreads();
    if (threadIdx.x == 0) {
        __threadfence();
        u64 arrive = atomicAdd(&g_init_cnt, 1ULL);
        u64 target = (arrive / NBLK + 1ULL) * NBLK;
        if (arrive + 1ULL != target) {
            volatile u64* p = (volatile u64*)&g_init_cnt;
            while (*p < target) { }
        }
        __threadfence();
    }
    __syncthreads();
}

#define BK1 16
#define LDA1 132

// =====================================================================
// Fused kernel: blocks 0-63 = recurrence (8 channels/CTA, fence-free
// scoped protocol, no smem staging), blocks 64-147 = gemm workers.
// =====================================================================
__global__ void __launch_bounds__(THR2, 1) fused_lstm_kernel(
    const float* __restrict__ X, const float* __restrict__ W,
    const float* __restrict__ bias, const int* __restrict__ lengths,
    float* __restrict__ out)
{
    extern __shared__ float smem[];
    const int tid = threadIdx.x;
    const int cta = blockIdx.x;

    if (cta >= NREC) {
        // ================== GEMM worker (R11 verbatim) ==================
        float* As = smem;
        float* Bs = smem + BK1 * LDA1;
        const int w = cta - NREC;
        const int tx = tid & 15, ty = tid >> 4;

        init_barrier_all();

        for (int it = w; it < TILES_TOTAL; it += NGEMM) {
            const int tau = it / TILES_PER_SLAB;
            const int r = it % TILES_PER_SLAB;
            const int b = r / 24;
            const int n = r % 24;
            const int n0 = n * 128;
            const size_t m0 = (size_t)b * NT + (size_t)tau * 128;

            const float* Xp = X + m0 * ND;
            const float* Wp = W + (size_t)n0 * ND;

            u64 accP[8][4];
#pragma unroll
            for (int i = 0; i < 8; i++)
#pragma unroll
                for (int j = 0; j < 4; j++) accP[i][j] = 0ULL;

            for (int kc = 0; kc < ND; kc += BK1) {
#pragma unroll
                for (int i = 0; i < 2; i++) {
                    int idx4 = tid + 256 * i;
                    int row = idx4 >> 2;
                    int kq = idx4 & 3;
                    float4 va = *(const float4*)(Xp + (size_t)row * ND + kc + kq * 4);
                    float4 vb = *(const float4*)(Wp + (size_t)row * ND + kc + kq * 4);
                    As[(kq * 4 + 0) * LDA1 + row] = va.x;
                    As[(kq * 4 + 1) * LDA1 + row] = va.y;
                    As[(kq * 4 + 2) * LDA1 + row] = va.z;
                    As[(kq * 4 + 3) * LDA1 + row] = va.w;
                    Bs[(kq * 4 + 0) * LDA1 + row] = vb.x;
                    Bs[(kq * 4 + 1) * LDA1 + row] = vb.y;
                    Bs[(kq * 4 + 2) * LDA1 + row] = vb.z;
                    Bs[(kq * 4 + 3) * LDA1 + row] = vb.w;
                }
                __syncthreads();
#pragma unroll
                for (int k = 0; k < BK1; k++) {
                    float a[8];
                    *(float4*)&a[0] = *(const float4*)&As[k * LDA1 + ty * 8];
                    *(float4*)&a[4] = *(const float4*)&As[k * LDA1 + ty * 8 + 4];
                    ulonglong2 b01 = *(const ulonglong2*)&Bs[k * LDA1 + tx * 8];
                    ulonglong2 b23 = *(const ulonglong2*)&Bs[k * LDA1 + tx * 8 + 4];
#pragma unroll
                    for (int i = 0; i < 8; i++) {
                        u64 ad = pack2(a[i], a[i]);
                        fma2(accP[i][0], b01.x, ad);
                        fma2(accP[i][1], b01.y, ad);
                        fma2(accP[i][2], b23.x, ad);
                        fma2(accP[i][3], b23.y, ad);
                    }
                }
                __syncthreads();
            }

            float bv[8];
#pragma unroll
            for (int j = 0; j < 8; j++) bv[j] = bias[n0 + tx * 8 + j];
#pragma unroll
            for (int i = 0; i < 8; i++) {
                float c[8];
#pragma unroll
                for (int jp = 0; jp < 4; jp++)
                    unpack2(accP[i][jp], c[2 * jp], c[2 * jp + 1]);
                size_t m = m0 + ty * 8 + i;
                float* op = g_pi + m * SIXH + n0 + tx * 8;
                float4 r0 = make_float4(c[0] + bv[0], c[1] + bv[1],
                                        c[2] + bv[2], c[3] + bv[3]);
                float4 r1 = make_float4(c[4] + bv[4], c[5] + bv[5],
                                        c[6] + bv[6], c[7] + bv[7]);
                *(float4*)op = r0;
                *(float4*)(op + 4) = r1;
            }

            __threadfence();
            __syncthreads();
            if (tid == 0) {
                asm volatile("red.release.gpu.global.add.u64 [%0], 1;"
                             :: "l"(&g_slab_cnt[tau]) : "memory");
            }
        }
        return;
    }

    // ============ recurrence CTA: lean local chain ============
    float* sh_wt = smem;                          // [512][48] channel-pair W
    u64*   red   = (u64*)(smem + 24576);          // [16b*5g*4jp][9] pairs
    __shared__ u64 s_slab[NSLAB];
    __shared__ u64 s_base;
    __shared__ unsigned s_flag;                   // local fanout flag

    const int jo_base = cta * 8;
    const unsigned flag_addr =
        (unsigned)__cvta_generic_to_shared(&s_flag);

    // persistent W slice (channel-pair layout, R11 verbatim)
    for (int p = tid; p < 40 * 512; p += THR2) {
        int k = p & 511;
        int r = p >> 9;          // 0..39
        int g = r / 8;
        int rc = r & 7;
        int jp = rc >> 1, c = rc & 1;
        sh_wt[k * 48 + jp * 12 + g * 2 + c] =
            W[(size_t)(g * NH + jo_base + 2 * jp + c) * ND + k];
    }

    if (tid < NSLAB) {
        u64 v;
        asm volatile("ld.global.cg.u64 %0, [%1];" : "=l"(v)
                     : "l"(&g_slab_cnt[tid]) : "memory");
        s_slab[tid] = v;
    }
    if (tid == 0) {
        u64 v;
        asm volatile("ld.global.cg.u64 %0, [%1];" : "=l"(v)
                     : "l"(&g_cnt) : "memory");
        s_base = v;
        s_flag = 0;
    }

    // combine-thread persistent state (128 threads: b_c=tid>>3, ch=tid&7)
    int b_c = 0, jo_c = 0, len_c = 0;
    float bias5[5] = {0, 0, 0, 0, 0};
    float c_reg = 0.0f;
    if (tid < 128) {
        b_c = tid >> 3;
        jo_c = jo_base + (tid & 7);
#pragma unroll
        for (int g = 0; g < 5; g++) bias5[g] = bias[g * NH + jo_c];
        len_c = lengths[b_c];
    }

    // publish h_0 = zeros (splatted, 128 u64 per CTA)
    if (tid < 128) g_h2[0][jo_c * NB + b_c] = 0ULL;
    init_barrier_all();   // makes zeros + bases globally visible

    const u64 base = s_base;
    const int warp = tid >> 5, lane = tid & 31;
    const int bg = lane >> 2;          // batch pair {2bg, 2bg+1}
    const int jp = lane & 3;           // channel pair {2jp, 2jp+1}
    const float* wp0 = sh_wt + (size_t)warp * 64 * 48 + jp * 12;

    for (int t = 0; t < NT; t++) {
        // slab gate before each 128-step PI slab
        if ((t & 127) == 0) {
            if (tid == 0) {
                int tau = t >> 7;
                u64 tgt = s_slab[tau] + (u64)TILES_PER_SLAB;
                u64 v;
                do {
                    asm volatile("ld.global.acquire.gpu.u64 %0, [%1];"
                                 : "=l"(v) : "l"(&g_slab_cnt[tau]) : "memory");
                } while (v < tgt);
            }
            __syncthreads();
        }

        // PI(t) prefetch (flies during the spin below)
        float pi5[5] = {0, 0, 0, 0, 0}, pi6 = 0.0f;
        if (tid < 128) {
            const float* pr = g_pi + ((size_t)b_c * NT + t) * SIXH + jo_c;
#pragma unroll
            for (int g = 0; g < 5; g++) pi5[g] = pr[g * NH];
            pi6 = pr[5 * NH];
        }

        // --- wait for h(t): warp0 polls L2 counter, fans out via smem ---
        if (warp == 0) {
            if (lane == 0) {
                u64 tgt = base + (u64)NREC * (u64)t;
                u64 v;
                do {
                    asm volatile("ld.global.acquire.gpu.u64 %0, [%1];"
                                 : "=l"(v) : "l"(&g_cnt) : "memory");
                } while (v < tgt);
                unsigned fv = (unsigned)(t + 1);
                asm volatile("st.release.cta.shared::cta.u32 [%0], %1;"
                             :: "r"(flag_addr), "r"(fv) : "memory");
            }
            __syncwarp();
        } else {
            if (lane == 0) {
                unsigned f;
                do {
                    asm volatile("ld.acquire.cta.shared::cta.u32 %0, [%1];"
                                 : "=r"(f) : "r"(flag_addr) : "memory");
                } while ((int)f < t + 1);
            }
            __syncwarp();
        }

        // --- compute directly from global h2 (L2), no staging ---
        u64 acc[10];
#pragma unroll
        for (int i = 0; i < 10; i++) acc[i] = 0ULL;
        {
            const u64* hp = g_h2[t & 1] + (size_t)warp * 64 * NB + 2 * bg;
            const float* wp = wp0;
#pragma unroll 8
            for (int kk = 0; kk < 64; kk++) {
                u64 h00 = __ldcg(hp);        // {h_b0, h_b0}
                u64 h11 = __ldcg(hp + 1);    // {h_b1, h_b1}
                ulonglong2 wA = *(const ulonglong2*)wp;        // g0,g1:{c0,c1}
                ulonglong2 wB = *(const ulonglong2*)(wp + 4);  // g2,g3
                u64 wC = *(const u64*)(wp + 8);                // g4
                fma2(acc[0], wA.x, h00);
                fma2(acc[1], wA.y, h00);
                fma2(acc[2], wB.x, h00);
                fma2(acc[3], wB.y, h00);
                fma2(acc[4], wC, h00);
                fma2(acc[5], wA.x, h11);
                fma2(acc[6], wA.y, h11);
                fma2(acc[7], wB.x, h11);
                fma2(acc[8], wB.y, h11);
                fma2(acc[9], wC, h11);
                hp += NB;
                wp += 48;
            }
        }

        // partials: red[((b*5+g)*4+jp)*9 + warp] = {c0,c1}
        {
            int rb0 = ((2 * bg) * 5) * 4 + jp;
            int rb1 = ((2 * bg + 1) * 5) * 4 + jp;
#pragma unroll
            for (int g = 0; g < 5; g++) {
                red[(rb0 + g * 4) * 9 + warp] = acc[g];
                red[(rb1 + g * 4) * 9 + warp] = acc[5 + g];
            }
        }
        __syncthreads();   // the ONLY CTA-wide sync per step

        // --- combine + publish (warps 0-3); warps 4-7 loop to next spin ---
        if (tid < 128) {
            const float* redf = (const float*)red;
            int jpc = (tid & 7) >> 1, e = tid & 1;
            float gv[5];
#pragma unroll
            for (int g = 0; g < 5; g++) {
                const float* rp = redf + (((b_c * 5 + g) * 4 + jpc) * 9) * 2 + e;
                float s = ((rp[0] + rp[2]) + (rp[4] + rp[6])) +
                          ((rp[8] + rp[10]) + (rp[12] + rp[14]));
                gv[g] = s + bias5[g] + pi5[g];
            }
            float ig = sigf(gv[0]);
            float fg = sigf(gv[1]);
            float mi = tanh_acc(gv[2]);
            float og = sigf(gv[3]);
            float hwg = sigf(gv[4]);
            float mem = fmaf(ig, mi, fg * c_reg);
            float o_ = og * tanh_acc(mem);
            o_ = fmaf(hwg, o_ - pi6, pi6);
            if (t >= len_c) { o_ = 0.0f; mem = 0.0f; }
            c_reg = mem;

            u64 oo = pack2(o_, o_);
            asm volatile("st.relaxed.gpu.global.u64 [%0], %1;"
                         :: "l"(&g_h2[(t + 1) & 1][jo_c * NB + b_c]),
                            "l"(oo) : "memory");
            out[((size_t)b_c * NT + t) * NH + jo_c] = o_;

            asm volatile("bar.sync 1, 128;" ::: "memory");
            if (tid == 0) {
                asm volatile("red.release.gpu.global.add.u64 [%0], 1;"
                             :: "l"(&g_cnt) : "memory");
            }
        }
    }
}

// =====================================================================
// launch
// =====================================================================
extern "C" void kernel_launch(void* const* d_in, const int* in_sizes, int n_in,
                              void* d_out, int out_size) {
    const float* x = (const float*)d_in[0];
    const int* lengths = (const int*)d_in[1];
    const float* W = (const float*)d_in[2];
    const float* bias = (const float*)d_in[3];
    float* out = (float*)d_out;

    static bool attr_done = false;
    if (!attr_done) {
        cudaFuncSetAttribute(fused_lstm_kernel,
                             cudaFuncAttributeMaxDynamicSharedMemorySize,
                             SMEM2_BYTES);
        attr_done = true;
    }

    fused_lstm_kernel<<<NBLK, THR2, SMEM2_BYTES>>>(x, W, bias, lengths, out);
}

// round 14
// speedup vs baseline: 1.7758x; 1.3291x over previous
#include <cuda_runtime.h>
#include <math.h>

#define NB 16
#define NT 2048
#define ND 512
#define NH 512
#define SIXH 3072
#define MROWS (NB * NT)   // 32768

#define NREC 64           // recurrence CTAs (8 channels each)
#define NGEMM 84          // gemm worker CTAs
#define NBLK (NREC + NGEMM)   // 148 == SM count -> all co-resident @ 1 CTA/SM
#define THR2 256

#define NSLAB 16
#define TILES_TOTAL 6144      // 16 b x 16 tau x 24 n
#define TILES_PER_SLAB 384    // 16 b x 24 n

// rec smem: sh_wt 512*48 | sh_h 512*16 | red 2880 u64 (5760 floats)
#define SMEM2_FLOATS (24576 + 8192 + 5760)
#define SMEM2_BYTES (SMEM2_FLOATS * 4)

typedef unsigned long long u64;

// ---------------- device scratch ----------------
__device__ float g_pi[(size_t)MROWS * SIXH];   // PI = X @ W^T + b
__device__ float g_h[2][ND * NB];              // h double buffer, [k][b]
__device__ u64 g_cnt;                          // step counter (monotonic)
__device__ u64 g_init_cnt;                     // init barrier (148 CTAs)
__device__ u64 g_slab_cnt[NSLAB];              // slab-complete counters

// ---------------- packed f32x2 helpers ----------------
__device__ __forceinline__ u64 pack2(float lo, float hi) {
    u64 r;
    asm("mov.b64 %0, {%1, %2};" : "=l"(r) : "f"(lo), "f"(hi));
    return r;
}
__device__ __forceinline__ void unpack2(u64 v, float& lo, float& hi) {
    asm("mov.b64 {%0, %1}, %2;" : "=f"(lo), "=f"(hi) : "l"(v));
}
__device__ __forceinline__ void fma2(u64& d, u64 a, u64 b) {
    asm("fma.rn.f32x2 %0, %1, %2, %0;" : "+l"(d) : "l"(a), "l"(b));
}

__device__ __forceinline__ float sigf(float x) {
    return 1.0f / (1.0f + __expf(-x));
}
__device__ __forceinline__ float tanh_acc(float x) {
    float e = __expf(-2.0f * fabsf(x));
    float t = (1.0f - e) / (1.0f + e);
    return x >= 0.0f ? t : -t;
}

// init barrier across ALL 148 CTAs (monotonic, replay-safe)
__device__ __forceinline__ void init_barrier_all() {
    __syncthreads();
    if (threadIdx.x == 0) {
        __threadfence();
        u64 arrive = atomicAdd(&g_init_cnt, 1ULL);
        u64 target = (arrive / NBLK + 1ULL) * NBLK;
        if (arrive + 1ULL != target) {
            volatile u64* p = (volatile u64*)&g_init_cnt;
            while (*p < target) { }
        }
        __threadfence();
    }
    __syncthreads();
}

#define BK1 16
#define LDA1 132

// =====================================================================
// Fused kernel: blocks 0-63 = recurrence (R11 compute core + fence-free
// R13 protocol + per-warp staging), blocks 64-147 = gemm workers.
// =====================================================================
__global__ void __launch_bounds__(THR2, 1) fused_lstm_kernel(
    const float* __restrict__ X, const float* __restrict__ W,
    const float* __restrict__ bias, const int* __restrict__ lengths,
    float* __restrict__ out)
{
    extern __shared__ float smem[];
    const int tid = threadIdx.x;
    const int cta = blockIdx.x;

    if (cta >= NREC) {
        // ================== GEMM worker (R11/R13 verbatim) ==================
        float* As = smem;
        float* Bs = smem + BK1 * LDA1;
        const int w = cta - NREC;
        const int tx = tid & 15, ty = tid >> 4;

        init_barrier_all();

        for (int it = w; it < TILES_TOTAL; it += NGEMM) {
            const int tau = it / TILES_PER_SLAB;
            const int r = it % TILES_PER_SLAB;
            const int b = r / 24;
            const int n = r % 24;
            const int n0 = n * 128;
            const size_t m0 = (size_t)b * NT + (size_t)tau * 128;

            const float* Xp = X + m0 * ND;
            const float* Wp = W + (size_t)n0 * ND;

            u64 accP[8][4];
#pragma unroll
            for (int i = 0; i < 8; i++)
#pragma unroll
                for (int j = 0; j < 4; j++) accP[i][j] = 0ULL;

            for (int kc = 0; kc < ND; kc += BK1) {
#pragma unroll
                for (int i = 0; i < 2; i++) {
                    int idx4 = tid + 256 * i;
                    int row = idx4 >> 2;
                    int kq = idx4 & 3;
                    float4 va = *(const float4*)(Xp + (size_t)row * ND + kc + kq * 4);
                    float4 vb = *(const float4*)(Wp + (size_t)row * ND + kc + kq * 4);
                    As[(kq * 4 + 0) * LDA1 + row] = va.x;
                    As[(kq * 4 + 1) * LDA1 + row] = va.y;
                    As[(kq * 4 + 2) * LDA1 + row] = va.z;
                    As[(kq * 4 + 3) * LDA1 + row] = va.w;
                    Bs[(kq * 4 + 0) * LDA1 + row] = vb.x;
                    Bs[(kq * 4 + 1) * LDA1 + row] = vb.y;
                    Bs[(kq * 4 + 2) * LDA1 + row] = vb.z;
                    Bs[(kq * 4 + 3) * LDA1 + row] = vb.w;
                }
                __syncthreads();
#pragma unroll
                for (int k = 0; k < BK1; k++) {
                    float a[8];
                    *(float4*)&a[0] = *(const float4*)&As[k * LDA1 + ty * 8];
                    *(float4*)&a[4] = *(const float4*)&As[k * LDA1 + ty * 8 + 4];
                    ulonglong2 b01 = *(const ulonglong2*)&Bs[k * LDA1 + tx * 8];
                    ulonglong2 b23 = *(const ulonglong2*)&Bs[k * LDA1 + tx * 8 + 4];
#pragma unroll
                    for (int i = 0; i < 8; i++) {
                        u64 ad = pack2(a[i], a[i]);
                        fma2(accP[i][0], b01.x, ad);
                        fma2(accP[i][1], b01.y, ad);
                        fma2(accP[i][2], b23.x, ad);
                        fma2(accP[i][3], b23.y, ad);
                    }
                }
                __syncthreads();
            }

            float bv[8];
#pragma unroll
            for (int j = 0; j < 8; j++) bv[j] = bias[n0 + tx * 8 + j];
#pragma unroll
            for (int i = 0; i < 8; i++) {
                float c[8];
#pragma unroll
                for (int jp = 0; jp < 4; jp++)
                    unpack2(accP[i][jp], c[2 * jp], c[2 * jp + 1]);
                size_t m = m0 + ty * 8 + i;
                float* op = g_pi + m * SIXH + n0 + tx * 8;
                float4 r0 = make_float4(c[0] + bv[0], c[1] + bv[1],
                                        c[2] + bv[2], c[3] + bv[3]);
                float4 r1 = make_float4(c[4] + bv[4], c[5] + bv[5],
                                        c[6] + bv[6], c[7] + bv[7]);
                *(float4*)op = r0;
                *(float4*)(op + 4) = r1;
            }

            __threadfence();
            __syncthreads();
            if (tid == 0) {
                asm volatile("red.release.gpu.global.add.u64 [%0], 1;"
                             :: "l"(&g_slab_cnt[tau]) : "memory");
            }
        }
        return;
    }

    // ============ recurrence CTA ============
    float* sh_wt = smem;                          // [512][48] channel-pair W
    float* sh_h  = smem + 24576;                  // [512][16] h staging
    u64*   red   = (u64*)(smem + 24576 + 8192);   // [16b*5g*4jp][9] pairs
    __shared__ u64 s_slab[NSLAB];
    __shared__ u64 s_base;
    __shared__ unsigned s_flag;

    const int jo_base = cta * 8;
    const unsigned flag_addr =
        (unsigned)__cvta_generic_to_shared(&s_flag);

    // persistent W slice (channel-pair layout, R11 verbatim)
    for (int p = tid; p < 40 * 512; p += THR2) {
        int k = p & 511;
        int r = p >> 9;          // 0..39
        int g = r / 8;
        int rc = r & 7;
        int jp = rc >> 1, c = rc & 1;
        sh_wt[k * 48 + jp * 12 + g * 2 + c] =
            W[(size_t)(g * NH + jo_base + 2 * jp + c) * ND + k];
    }

    if (tid < NSLAB) {
        u64 v;
        asm volatile("ld.global.cg.u64 %0, [%1];" : "=l"(v)
                     : "l"(&g_slab_cnt[tid]) : "memory");
        s_slab[tid] = v;
    }
    if (tid == 0) {
        u64 v;
        asm volatile("ld.global.cg.u64 %0, [%1];" : "=l"(v)
                     : "l"(&g_cnt) : "memory");
        s_base = v;
        s_flag = 0;
    }

    // combine-thread persistent state (128 threads: b_c=tid>>3, ch=tid&7)
    int b_c = 0, jo_c = 0, len_c = 0;
    float bias5[5] = {0, 0, 0, 0, 0};
    float c_reg = 0.0f;
    if (tid < 128) {
        b_c = tid >> 3;
        jo_c = jo_base + (tid & 7);
#pragma unroll
        for (int g = 0; g < 5; g++) bias5[g] = bias[g * NH + jo_c];
        len_c = lengths[b_c];
    }

    // publish h_0 = zeros (128 floats per CTA)
    if (tid < 128) g_h[0][jo_c * NB + b_c] = 0.0f;
    init_barrier_all();   // makes zeros + bases globally visible

    const u64 base = s_base;
    const int warp = tid >> 5, lane = tid & 31;
    const int bg = lane & 7;   // batch pair {2bg, 2bg+1}
    const int jp = lane >> 3;  // channel pair {2jp, 2jp+1}
    const u64*   hp0 = (const u64*)sh_h + (size_t)warp * 64 * 8 + bg;
    const float* wp0 = sh_wt + (size_t)warp * 64 * 48 + jp * 12;

    for (int t = 0; t < NT; t++) {
        // slab gate before each 128-step PI slab
        if ((t & 127) == 0) {
            if (tid == 0) {
                int tau = t >> 7;
                u64 tgt = s_slab[tau] + (u64)TILES_PER_SLAB;
                u64 v;
                do {
                    asm volatile("ld.global.acquire.gpu.u64 %0, [%1];"
                                 : "=l"(v) : "l"(&g_slab_cnt[tau]) : "memory");
                } while (v < tgt);
            }
            __syncthreads();
        }

        // PI(t) prefetch (L1 first-touch is after its slab gate -> fresh)
        float pi5[5] = {0, 0, 0, 0, 0}, pi6 = 0.0f;
        if (tid < 128) {
            const float* pr = g_pi + ((size_t)b_c * NT + t) * SIXH + jo_c;
#pragma unroll
            for (int g = 0; g < 5; g++) pi5[g] = pr[g * NH];
            pi6 = pr[5 * NH];
        }

        // --- wait for h(t): warp0 acquire-polls counter, fans out via smem ---
        if (warp == 0) {
            if (lane == 0) {
                u64 tgt = base + (u64)NREC * (u64)t;
                u64 v;
                do {
                    asm volatile("ld.global.acquire.gpu.u64 %0, [%1];"
                                 : "=l"(v) : "l"(&g_cnt) : "memory");
                } while (v < tgt);
                unsigned fv = (unsigned)(t + 1);
                asm volatile("st.release.cta.shared::cta.u32 [%0], %1;"
                             :: "r"(flag_addr), "r"(fv) : "memory");
            }
            __syncwarp();
        } else {
            if (lane == 0) {
                unsigned f;
                do {
                    asm volatile("ld.acquire.cta.shared::cta.u32 %0, [%1];"
                                 : "=r"(f) : "r"(flag_addr) : "memory");
                } while ((int)f < t + 1);
            }
            __syncwarp();
        }

        // --- per-warp staging of own 64x16 h slab (L2-direct) ---
        {
            const float* hbuf = g_h[t & 1];
            const float4* src = (const float4*)(hbuf + warp * 1024);
            float4* dst = (float4*)(sh_h + warp * 1024);
#pragma unroll
            for (int i = 0; i < 8; i++)
                dst[i * 32 + lane] = __ldcg(src + i * 32 + lane);
        }
        __syncwarp();

        // --- K-split packed GEMM: 2 batches x 5 gates x {2 ch}, 64 k (R11) ---
        u64 acc[10];
#pragma unroll
        for (int i = 0; i < 10; i++) acc[i] = 0ULL;
        {
            const u64* hp = hp0;
            const float* wp = wp0;
#pragma unroll 8
            for (int kk = 0; kk < 64; kk++) {
                u64 hd = *hp;                                  // {h_b0, h_b1}
                float h0, h1;
                unpack2(hd, h0, h1);
                u64 h00 = pack2(h0, h0);
                u64 h11 = pack2(h1, h1);
                ulonglong2 wA = *(const ulonglong2*)wp;        // g0,g1:{c0,c1}
                ulonglong2 wB = *(const ulonglong2*)(wp + 4);  // g2,g3
                u64 wC = *(const u64*)(wp + 8);                // g4
                fma2(acc[0], wA.x, h00);
                fma2(acc[1], wA.y, h00);
                fma2(acc[2], wB.x, h00);
                fma2(acc[3], wB.y, h00);
                fma2(acc[4], wC, h00);
                fma2(acc[5], wA.x, h11);
                fma2(acc[6], wA.y, h11);
                fma2(acc[7], wB.x, h11);
                fma2(acc[8], wB.y, h11);
                fma2(acc[9], wC, h11);
                hp += 8;
                wp += 48;
            }
        }

        // partials: red[((b*5+g)*4+jp)*9 + warp] = {c0,c1}
        {
            int rb0 = ((2 * bg) * 5) * 4 + jp;
            int rb1 = ((2 * bg + 1) * 5) * 4 + jp;
#pragma unroll
            for (int g = 0; g < 5; g++) {
                red[(rb0 + g * 4) * 9 + warp] = acc[g];
                red[(rb1 + g * 4) * 9 + warp] = acc[5 + g];
            }
        }
        __syncthreads();   // the ONLY CTA-wide sync per step

        // --- combine + publish (warps 0-3); warps 4-7 loop to next spin ---
        if (tid < 128) {
            const float* redf = (const float*)red;
            int jpc = (tid & 7) >> 1, e = tid & 1;
            float gv[5];
#pragma unroll
            for (int g = 0; g < 5; g++) {
                const float* rp = redf + (((b_c * 5 + g) * 4 + jpc) * 9) * 2 + e;
                float s = ((rp[0] + rp[2]) + (rp[4] + rp[6])) +
                          ((rp[8] + rp[10]) + (rp[12] + rp[14]));
                gv[g] = s + bias5[g] + pi5[g];
            }
            float ig = sigf(gv[0]);
            float fg = sigf(gv[1]);
            float mi = tanh_acc(gv[2]);
            float og = sigf(gv[3]);
            float hwg = sigf(gv[4]);
            float mem = fmaf(ig, mi, fg * c_reg);
            float o_ = og * tanh_acc(mem);
            o_ = fmaf(hwg, o_ - pi6, pi6);
            if (t >= len_c) { o_ = 0.0f; mem = 0.0f; }
            c_reg = mem;

            asm volatile("st.relaxed.gpu.global.f32 [%0], %1;"
                         :: "l"(&g_h[(t + 1) & 1][jo_c * NB + b_c]),
                            "f"(o_) : "memory");

            asm volatile("bar.sync 1, 128;" ::: "memory");
            if (tid == 0) {
                asm volatile("red.release.gpu.global.add.u64 [%0], 1;"
                             :: "l"(&g_cnt) : "memory");
            }
            // off the critical path
            out[((size_t)b_c * NT + t) * NH + jo_c] = o_;
        }
    }
}

// =====================================================================
// launch
// =====================================================================
extern "C" void kernel_launch(void* const* d_in, const int* in_sizes, int n_in,
                              void* d_out, int out_size) {
    const float* x = (const float*)d_in[0];
    const int* lengths = (const int*)d_in[1];
    const float* W = (const float*)d_in[2];
    const float* bias = (const float*)d_in[3];
    float* out = (float*)d_out;

    static bool attr_done = false;
    if (!attr_done) {
        cudaFuncSetAttribute(fused_lstm_kernel,
                             cudaFuncAttributeMaxDynamicSharedMemorySize,
                             SMEM2_BYTES);
        attr_done = true;
    }

    fused_lstm_kernel<<<NBLK, THR2, SMEM2_BYTES>>>(x, W, bias, lengths, out);
}